// round 5
// baseline (speedup 1.0000x reference)
#include <cuda_runtime.h>
#include <math_constants.h>

#define NB 64
#define NM 1024
#define NN (NB*NM)      // 65536 nodes
#define NH 64
#define NK 16
#define HPAD 20         // padded k-stride for transposed hidden tile (msg)

#define TI 128          // knn: rows per block
#define TJ 64           // knn: cols per chunk

// ---------------- device scratch (static globals; no allocation) -------------
__device__ float g_h0[NN*NH];
__device__ float g_h1[NN*NH];
__device__ float g_a [NN*NH];
__device__ float g_e [NN*NH];
__device__ float g_sq[NN];
__device__ int   g_idx[NN*NK];

// ---------------- encoder: x[4] -> 32 -> 64 (ReLU both), + sqnorm ------------
__global__ void __launch_bounds__(256) enc_kernel(
    const float* __restrict__ x,
    const float* __restrict__ w1, const float* __restrict__ b1,
    const float* __restrict__ w2, const float* __restrict__ b2)
{
    __shared__ float w1s[4*32];
    __shared__ float b1s[32];
    __shared__ float w2s[32*64];
    __shared__ float b2s[64];
    int tid = threadIdx.x;
    if (tid < 128) w1s[tid] = w1[tid];
    if (tid < 32)  b1s[tid] = b1[tid];
    for (int q = tid; q < 32*64; q += 256) w2s[q] = w2[q];
    if (tid < 64)  b2s[tid] = b2[tid];
    __syncthreads();

    int n = blockIdx.x * 256 + tid;
    float4 xv = reinterpret_cast<const float4*>(x)[n];

    float hid[32];
#pragma unroll
    for (int o = 0; o < 32; o++) {
        float acc = b1s[o];
        acc += xv.x * w1s[o];
        acc += xv.y * w1s[32 + o];
        acc += xv.z * w1s[64 + o];
        acc += xv.w * w1s[96 + o];
        hid[o] = fmaxf(acc, 0.f);
    }

    float sq = 0.f;
    float4* outp = reinterpret_cast<float4*>(&g_h0[(size_t)n * NH]);
    const float4* w2v = reinterpret_cast<const float4*>(w2s);
    const float4* b2v = reinterpret_cast<const float4*>(b2s);
#pragma unroll
    for (int og = 0; og < 16; og++) {
        float4 acc = b2v[og];
#pragma unroll
        for (int j = 0; j < 32; j++) {
            float hv = hid[j];
            float4 wv = w2v[j*16 + og];
            acc.x += hv * wv.x; acc.y += hv * wv.y;
            acc.z += hv * wv.z; acc.w += hv * wv.w;
        }
        acc.x = fmaxf(acc.x, 0.f); acc.y = fmaxf(acc.y, 0.f);
        acc.z = fmaxf(acc.z, 0.f); acc.w = fmaxf(acc.w, 0.f);
        sq += acc.x*acc.x + acc.y*acc.y + acc.z*acc.z + acc.w*acc.w;
        outp[og] = acc;
    }
    g_sq[n] = sq;
}

// ---------------- kNN v2: register-blocked distance GEMM + fused top-16 ------
// block = 128 threads, handles 128 rows of one batch; loops over j in 64-chunks.
// Each thread owns an 8x8 accumulator tile (1 B/FMA smem traffic, FMA-balanced).
// After each chunk, thread t scans row t of the distance tile (conflict-free
// via XOR swizzle) and maintains its top-16 threshold-replace list in regs.
__global__ void __launch_bounds__(128) knn2_kernel(const float* __restrict__ h)
{
    extern __shared__ float sm[];
    float* his  = sm;                   // [64][TI]   k-major i tile (32 KB)
    float* hjs  = sm + 64*TI;           // [64][TJ]   k-major j tile (16 KB)
    float* dist = hjs + 64*TJ;          // [TJ][TI]   swizzled distance tile (32 KB)
    float* sqs  = dist + TJ*TI;         // [TJ]

    int tid    = threadIdx.x;
    int b      = blockIdx.x >> 3;
    int istrip = (blockIdx.x & 7) * TI;
    int iloc   = istrip + tid;          // local row this thread owns for selection
    const float* hb = h + (size_t)b * NM * NH;

    // load his: transpose rows [istrip..istrip+127] into [k][i]
    {
        const float4* src = reinterpret_cast<const float4*>(hb + (size_t)(istrip + tid) * NH);
#pragma unroll
        for (int c = 0; c < 16; c++) {
            float4 v = src[c];
            his[(4*c+0)*TI + tid] = v.x;
            his[(4*c+1)*TI + tid] = v.y;
            his[(4*c+2)*TI + tid] = v.z;
            his[(4*c+3)*TI + tid] = v.w;
        }
    }

    float bdist[NK]; int bidx[NK];
#pragma unroll
    for (int k = 0; k < NK; k++) { bdist[k] = CUDART_INF_F; bidx[k] = 0; }
    float worst = CUDART_INF_F; int wpos = 0;

    int ty = tid >> 3;        // 0..15 -> i-group (8 rows)
    int tx = tid & 7;         // 0..7  -> j-group (8 cols)

    for (int jb = 0; jb < NM; jb += TJ) {
        __syncthreads();      // prev-chunk scan (dist reads) done before reuse

        // load hjs chunk transposed + sq values
        {
            int r  = tid & 63;
            int ch = tid >> 6;
            const float4* src = reinterpret_cast<const float4*>(hb + (size_t)(jb + r) * NH);
#pragma unroll
            for (int t = 0; t < 8; t++) {
                int c = ch * 8 + t;
                float4 v = src[c];
                hjs[(4*c+0)*TJ + r] = v.x;
                hjs[(4*c+1)*TJ + r] = v.y;
                hjs[(4*c+2)*TJ + r] = v.z;
                hjs[(4*c+3)*TJ + r] = v.w;
            }
            if (tid < TJ) sqs[tid] = g_sq[b*NM + jb + tid];
        }
        __syncthreads();

        // GEMM: acc[ii][jj] = dot(h_i, h_j)
        float acc[8][8];
#pragma unroll
        for (int ii = 0; ii < 8; ii++)
#pragma unroll
            for (int jj = 0; jj < 8; jj++) acc[ii][jj] = 0.f;

        const float4* his4 = reinterpret_cast<const float4*>(his);
        const float4* hjs4 = reinterpret_cast<const float4*>(hjs);
#pragma unroll 4
        for (int k = 0; k < 64; k++) {
            float4 A0 = his4[k*(TI/4) + ty*2];
            float4 A1 = his4[k*(TI/4) + ty*2 + 1];
            float4 B0 = hjs4[k*(TJ/4) + tx*2];
            float4 B1 = hjs4[k*(TJ/4) + tx*2 + 1];
            float av[8] = {A0.x,A0.y,A0.z,A0.w,A1.x,A1.y,A1.z,A1.w};
            float bv[8] = {B0.x,B0.y,B0.z,B0.w,B1.x,B1.y,B1.z,B1.w};
#pragma unroll
            for (int ii = 0; ii < 8; ii++)
#pragma unroll
                for (int jj = 0; jj < 8; jj++)
                    acc[ii][jj] += av[ii] * bv[jj];
        }

        // write distances to swizzled [j][i] tile: word = j*TI + (i ^ ((j>>3)<<2))
#pragma unroll
        for (int jj = 0; jj < 8; jj++) {
            int j = tx*8 + jj;
            float sqv = sqs[j];
            int swz = tx << 2;          // (j>>3)<<2, j>>3 == tx here
#pragma unroll
            for (int q = 0; q < 2; q++) {
                int iw = (ty*8 + q*4) ^ swz;
                float4 v;
                v.x = sqv - 2.f*acc[q*4+0][jj];
                v.y = sqv - 2.f*acc[q*4+1][jj];
                v.z = sqv - 2.f*acc[q*4+2][jj];
                v.w = sqv - 2.f*acc[q*4+3][jj];
                *reinterpret_cast<float4*>(dist + j*TI + iw) = v;
            }
        }
        __syncthreads();

        // selection: thread tid scans row tid of dist tile
#pragma unroll 4
        for (int jj = 0; jj < TJ; jj++) {
            float d = dist[jj*TI + (tid ^ ((jj >> 3) << 2))];
            int jl = jb + jj;
            if (d < worst && jl != iloc) {
#pragma unroll
                for (int k = 0; k < NK; k++) if (k == wpos) { bdist[k] = d; bidx[k] = jl; }
                worst = bdist[0]; wpos = 0;
#pragma unroll
                for (int k = 1; k < NK; k++) if (bdist[k] > worst) { worst = bdist[k]; wpos = k; }
            }
        }
    }

    int i = b*NM + iloc;
#pragma unroll
    for (int k = 0; k < NK; k++) g_idx[(size_t)i*NK + k] = b*NM + bidx[k];
}

// ---------------- prep: a = h@W1[:64] + b1,  e = h@W1[64:] -------------------
__global__ void __launch_bounds__(256) prep_kernel(
    const float* __restrict__ h,
    const float* __restrict__ w1, const float* __restrict__ b1)
{
    __shared__ float w1s[128*64];
    __shared__ float b1s[64];
    for (int q = threadIdx.x; q < 128*64; q += 256) w1s[q] = w1[q];
    if (threadIdx.x < 64) b1s[threadIdx.x] = b1[threadIdx.x];
    __syncthreads();

    int n = blockIdx.x * 256 + threadIdx.x;
    float hv[NH];
    {
        const float4* src = reinterpret_cast<const float4*>(h + (size_t)n * NH);
#pragma unroll
        for (int f = 0; f < 16; f++) {
            float4 v = src[f];
            hv[f*4+0] = v.x; hv[f*4+1] = v.y; hv[f*4+2] = v.z; hv[f*4+3] = v.w;
        }
    }

    const float4* wA = reinterpret_cast<const float4*>(w1s);            // rows 0..63
    const float4* wB = reinterpret_cast<const float4*>(w1s + 64*64);    // rows 64..127
    const float4* b1v = reinterpret_cast<const float4*>(b1s);
    float4* ap = reinterpret_cast<float4*>(&g_a[(size_t)n * NH]);
    float4* ep = reinterpret_cast<float4*>(&g_e[(size_t)n * NH]);

#pragma unroll 2
    for (int og = 0; og < 16; og++) {
        float4 acc = b1v[og];
#pragma unroll 8
        for (int f = 0; f < 64; f++) {
            float x = hv[f];
            float4 wv = wA[f*16 + og];
            acc.x += x*wv.x; acc.y += x*wv.y; acc.z += x*wv.z; acc.w += x*wv.w;
        }
        ap[og] = acc;
    }
#pragma unroll 2
    for (int og = 0; og < 16; og++) {
        float4 acc = make_float4(0.f, 0.f, 0.f, 0.f);
#pragma unroll 8
        for (int f = 0; f < 64; f++) {
            float x = hv[f];
            float4 wv = wB[f*16 + og];
            acc.x += x*wv.x; acc.y += x*wv.y; acc.z += x*wv.z; acc.w += x*wv.w;
        }
        ep[og] = acc;
    }
}

// ---------------- msg: hidden = relu(a_i + e_j - e_i); out = max_k hidden@W2+b2
// block = 128 threads = 4 warps; warp handles one node.
__global__ void __launch_bounds__(128) msg_kernel(
    const float* __restrict__ w2, const float* __restrict__ b2,
    float* __restrict__ hout)
{
    __shared__ float w2s[64*64];
    __shared__ float hidden[4][64*HPAD];     // [warp][o*HPAD + k]
    for (int q = threadIdx.x; q < 64*64; q += 128) w2s[q] = w2[q];
    __syncthreads();

    int warp = threadIdx.x >> 5;
    int l    = threadIdx.x & 31;
    int i    = blockIdx.x * 4 + warp;

    float a0 = g_a[(size_t)i*NH + l],      a1 = g_a[(size_t)i*NH + 32 + l];
    float e0 = g_e[(size_t)i*NH + l],      e1 = g_e[(size_t)i*NH + 32 + l];
    int jreg = (l < NK) ? g_idx[(size_t)i*NK + l] : 0;

    float* hid = hidden[warp];
#pragma unroll
    for (int k = 0; k < NK; k++) {
        int j = __shfl_sync(0xffffffffu, jreg, k);
        float ej0 = g_e[(size_t)j*NH + l];
        float ej1 = g_e[(size_t)j*NH + 32 + l];
        hid[l*HPAD + k]        = fmaxf(a0 + ej0 - e0, 0.f);
        hid[(l+32)*HPAD + k]   = fmaxf(a1 + ej1 - e1, 0.f);
    }
    __syncwarp();

    float accL[NK], accH[NK];
#pragma unroll
    for (int k = 0; k < NK; k++) { accL[k] = 0.f; accH[k] = 0.f; }

#pragma unroll 2
    for (int o = 0; o < 64; o++) {
        float wl = w2s[o*64 + l];
        float wh = w2s[o*64 + 32 + l];
        const float4* hp = reinterpret_cast<const float4*>(hid + o*HPAD);
        float4 h0v = hp[0], h1v = hp[1], h2v = hp[2], h3v = hp[3];
        float hk[16] = { h0v.x,h0v.y,h0v.z,h0v.w, h1v.x,h1v.y,h1v.z,h1v.w,
                         h2v.x,h2v.y,h2v.z,h2v.w, h3v.x,h3v.y,h3v.z,h3v.w };
#pragma unroll
        for (int k = 0; k < NK; k++) {
            accL[k] += hk[k] * wl;
            accH[k] += hk[k] * wh;
        }
    }

    float m0 = accL[0], m1 = accH[0];
#pragma unroll
    for (int k = 1; k < NK; k++) { m0 = fmaxf(m0, accL[k]); m1 = fmaxf(m1, accH[k]); }
    m0 += b2[l];
    m1 += b2[32 + l];

    hout[(size_t)i*NH + l]      = m0;
    hout[(size_t)i*NH + 32 + l] = m1;

    float s = m0*m0 + m1*m1;
#pragma unroll
    for (int off = 16; off; off >>= 1) s += __shfl_xor_sync(0xffffffffu, s, off);
    if (l == 0) g_sq[i] = s;
}

// ---------------- pool + output MLP -----------------------------------------
__global__ void __launch_bounds__(256) pool_kernel(
    const float* __restrict__ h,
    const float* __restrict__ w1, const float* __restrict__ b1,
    const float* __restrict__ w2, const float* __restrict__ b2,
    float* __restrict__ out)
{
    __shared__ float part[256];
    __shared__ float g[64];
    int b = blockIdx.x, tid = threadIdx.x;
    int c = tid & 63, rb = tid >> 6;
    float s = 0.f;
    for (int r = rb; r < NM; r += 4) s += h[(size_t)(b*NM + r)*NH + c];
    part[tid] = s;
    __syncthreads();
    if (tid < 64) g[tid] = (part[tid] + part[tid+64] + part[tid+128] + part[tid+192]) * (1.f/NM);
    __syncthreads();
    if (tid < 32) {
        float acc = b1[tid];
#pragma unroll 8
        for (int f = 0; f < 64; f++) acc += g[f] * w1[f*32 + tid];
        acc = fmaxf(acc, 0.f);
        acc *= w2[tid];
#pragma unroll
        for (int off = 16; off; off >>= 1) acc += __shfl_xor_sync(0xffffffffu, acc, off);
        if (tid == 0) out[b] = acc + b2[0];
    }
}

// ---------------- launch -----------------------------------------------------
extern "C" void kernel_launch(void* const* d_in, const int* in_sizes, int n_in,
                              void* d_out, int out_size)
{
    const float* x      = (const float*)d_in[0];
    const float* enc_w1 = (const float*)d_in[2];
    const float* enc_b1 = (const float*)d_in[3];
    const float* enc_w2 = (const float*)d_in[4];
    const float* enc_b2 = (const float*)d_in[5];
    const float* ec1_w1 = (const float*)d_in[6];
    const float* ec1_b1 = (const float*)d_in[7];
    const float* ec1_w2 = (const float*)d_in[8];
    const float* ec1_b2 = (const float*)d_in[9];
    const float* ec2_w1 = (const float*)d_in[10];
    const float* ec2_b1 = (const float*)d_in[11];
    const float* ec2_w2 = (const float*)d_in[12];
    const float* ec2_b2 = (const float*)d_in[13];
    const float* out_w1 = (const float*)d_in[14];
    const float* out_b1 = (const float*)d_in[15];
    const float* out_w2 = (const float*)d_in[16];
    const float* out_b2 = (const float*)d_in[17];
    float* out = (float*)d_out;

    float *h0, *h1;
    cudaGetSymbolAddress((void**)&h0, g_h0);
    cudaGetSymbolAddress((void**)&h1, g_h1);

    const int KNN_SMEM = (64*TI + 64*TJ + TJ*TI + TJ) * sizeof(float);  // 82176 B
    cudaFuncSetAttribute(knn2_kernel, cudaFuncAttributeMaxDynamicSharedMemorySize, KNN_SMEM);

    // encoder -> h0 (+ sqnorms)
    enc_kernel<<<NN/256, 256>>>(x, enc_w1, enc_b1, enc_w2, enc_b2);
    // EdgeConv 1
    knn2_kernel<<<NB*8, 128, KNN_SMEM>>>(h0);
    prep_kernel<<<NN/256, 256>>>(h0, ec1_w1, ec1_b1);
    msg_kernel<<<NN/4, 128>>>(ec1_w2, ec1_b2, h1);
    // EdgeConv 2
    knn2_kernel<<<NB*8, 128, KNN_SMEM>>>(h1);
    prep_kernel<<<NN/256, 256>>>(h1, ec2_w1, ec2_b1);
    msg_kernel<<<NN/4, 128>>>(ec2_w2, ec2_b2, h0);   // reuse h0 as h2
    // pool + output MLP
    pool_kernel<<<NB, 256>>>(h0, out_w1, out_b1, out_w2, out_b2, out);
}

// round 9
// speedup vs baseline: 1.0623x; 1.0623x over previous
#include <cuda_runtime.h>
#include <math_constants.h>

#define NB 64
#define NM 1024
#define NN (NB*NM)      // 65536 nodes
#define NH 64
#define NK 16
#define HPAD 20         // padded k-stride for transposed hidden tile (msg)

// ---------------- packed f32x2 helpers (Blackwell) ---------------------------
__device__ __forceinline__ unsigned long long pack2(float lo, float hi) {
    unsigned long long r;
    asm("mov.b64 %0, {%1, %2};" : "=l"(r) : "r"(__float_as_uint(lo)), "r"(__float_as_uint(hi)));
    return r;
}
__device__ __forceinline__ void fma2(unsigned long long& d,
                                     unsigned long long a, unsigned long long b) {
    asm("fma.rn.f32x2 %0, %1, %2, %3;" : "=l"(d) : "l"(a), "l"(b), "l"(d));
}
__device__ __forceinline__ float2 unpack2(unsigned long long v) {
    unsigned int lo, hi;
    asm("mov.b64 {%0, %1}, %2;" : "=r"(lo), "=r"(hi) : "l"(v));
    return make_float2(__uint_as_float(lo), __uint_as_float(hi));
}

// ---------------- device scratch (static globals; no allocation) -------------
__device__ float g_h0[NN*NH];
__device__ float g_h1[NN*NH];
__device__ float g_a [NN*NH];
__device__ float g_e [NN*NH];
__device__ float g_sq[NN];
__device__ int   g_idx[NN*NK];

// ---------------- encoder: x[4] -> 32 -> 64 (ReLU both), + sqnorm ------------
__global__ void __launch_bounds__(256) enc_kernel(
    const float* __restrict__ x,
    const float* __restrict__ w1, const float* __restrict__ b1,
    const float* __restrict__ w2, const float* __restrict__ b2)
{
    __shared__ float w1s[4*32];
    __shared__ float b1s[32];
    __shared__ float w2s[32*64];
    __shared__ float b2s[64];
    int tid = threadIdx.x;
    if (tid < 128) w1s[tid] = w1[tid];
    if (tid < 32)  b1s[tid] = b1[tid];
    for (int q = tid; q < 32*64; q += 256) w2s[q] = w2[q];
    if (tid < 64)  b2s[tid] = b2[tid];
    __syncthreads();

    int n = blockIdx.x * 256 + tid;
    float4 xv = reinterpret_cast<const float4*>(x)[n];

    float hid[32];
#pragma unroll
    for (int o = 0; o < 32; o++) {
        float acc = b1s[o];
        acc += xv.x * w1s[o];
        acc += xv.y * w1s[32 + o];
        acc += xv.z * w1s[64 + o];
        acc += xv.w * w1s[96 + o];
        hid[o] = fmaxf(acc, 0.f);
    }

    float sq = 0.f;
    float4* outp = reinterpret_cast<float4*>(&g_h0[(size_t)n * NH]);
    const float4* w2v = reinterpret_cast<const float4*>(w2s);
    const float4* b2v = reinterpret_cast<const float4*>(b2s);
#pragma unroll
    for (int og = 0; og < 16; og++) {
        float4 acc = b2v[og];
#pragma unroll
        for (int j = 0; j < 32; j++) {
            float hv = hid[j];
            float4 wv = w2v[j*16 + og];
            acc.x += hv * wv.x; acc.y += hv * wv.y;
            acc.z += hv * wv.z; acc.w += hv * wv.w;
        }
        acc.x = fmaxf(acc.x, 0.f); acc.y = fmaxf(acc.y, 0.f);
        acc.z = fmaxf(acc.z, 0.f); acc.w = fmaxf(acc.w, 0.f);
        sq += acc.x*acc.x + acc.y*acc.y + acc.z*acc.z + acc.w*acc.w;
        outp[og] = acc;
    }
    g_sq[n] = sq;
}

// ---------------- kNN v1 + f32x2: per row, top-16 smallest (sq_j - 2*dot) ----
// block = 128 threads = 128 rows of one batch; 8 blocks per batch.
// Inner dot uses packed fma.rn.f32x2: 32 packed FMA + 16 LDS.128 per candidate.
__global__ void __launch_bounds__(128) knn_kernel(const float* __restrict__ h)
{
    __shared__ float hs[32*NH];
    __shared__ float sqs[32];

    int b  = blockIdx.x >> 3;
    int il = (blockIdx.x & 7) * 128 + threadIdx.x;   // local row index
    int i  = b * NM + il;

    // own row, packed into 32 f32x2 registers
    unsigned long long hi2[32];
    {
        const ulonglong2* src = reinterpret_cast<const ulonglong2*>(h + (size_t)i * NH);
#pragma unroll
        for (int f = 0; f < 16; f++) {
            ulonglong2 v = src[f];
            hi2[2*f]   = v.x;
            hi2[2*f+1] = v.y;
        }
    }

    float dist[NK]; int idx[NK];
#pragma unroll
    for (int k = 0; k < NK; k++) { dist[k] = CUDART_INF_F; idx[k] = 0; }
    float worst = CUDART_INF_F; int wpos = 0;

    for (int jt = 0; jt < NM; jt += 32) {
        __syncthreads();
        {
            const float4* src = reinterpret_cast<const float4*>(h + (size_t)(b*NM + jt) * NH);
            float4* dst = reinterpret_cast<float4*>(hs);
#pragma unroll
            for (int it = 0; it < 4; it++) dst[threadIdx.x + 128*it] = src[threadIdx.x + 128*it];
            if (threadIdx.x < 32) sqs[threadIdx.x] = g_sq[b*NM + jt + threadIdx.x];
        }
        __syncthreads();

#pragma unroll 4
        for (int c = 0; c < 32; c++) {
            const ulonglong2* hv = reinterpret_cast<const ulonglong2*>(hs + c*NH);
            unsigned long long a0 = 0ull, a1 = 0ull, a2 = 0ull, a3 = 0ull;
#pragma unroll
            for (int f = 0; f < 16; f += 2) {
                ulonglong2 v0 = hv[f];
                ulonglong2 v1 = hv[f+1];
                fma2(a0, hi2[2*f],   v0.x);
                fma2(a1, hi2[2*f+1], v0.y);
                fma2(a2, hi2[2*f+2], v1.x);
                fma2(a3, hi2[2*f+3], v1.y);
            }
            float2 p0 = unpack2(a0), p1 = unpack2(a1), p2 = unpack2(a2), p3 = unpack2(a3);
            float dot = ((p0.x + p0.y) + (p1.x + p1.y)) + ((p2.x + p2.y) + (p3.x + p3.y));
            float d = sqs[c] - 2.f * dot;
            int j = jt + c;
            if (d < worst && j != il) {
#pragma unroll
                for (int k = 0; k < NK; k++) if (k == wpos) { dist[k] = d; idx[k] = j; }
                worst = dist[0]; wpos = 0;
#pragma unroll
                for (int k = 1; k < NK; k++) if (dist[k] > worst) { worst = dist[k]; wpos = k; }
            }
        }
    }
#pragma unroll
    for (int k = 0; k < NK; k++) g_idx[(size_t)i*NK + k] = b*NM + idx[k];
}

// ---------------- prep: a = h@W1[:64] + b1,  e = h@W1[64:] -------------------
__global__ void __launch_bounds__(256) prep_kernel(
    const float* __restrict__ h,
    const float* __restrict__ w1, const float* __restrict__ b1)
{
    __shared__ float w1s[128*64];
    __shared__ float b1s[64];
    for (int q = threadIdx.x; q < 128*64; q += 256) w1s[q] = w1[q];
    if (threadIdx.x < 64) b1s[threadIdx.x] = b1[threadIdx.x];
    __syncthreads();

    int n = blockIdx.x * 256 + threadIdx.x;
    float hv[NH];
    {
        const float4* src = reinterpret_cast<const float4*>(h + (size_t)n * NH);
#pragma unroll
        for (int f = 0; f < 16; f++) {
            float4 v = src[f];
            hv[f*4+0] = v.x; hv[f*4+1] = v.y; hv[f*4+2] = v.z; hv[f*4+3] = v.w;
        }
    }

    const float4* wA = reinterpret_cast<const float4*>(w1s);            // rows 0..63
    const float4* wB = reinterpret_cast<const float4*>(w1s + 64*64);    // rows 64..127
    const float4* b1v = reinterpret_cast<const float4*>(b1s);
    float4* ap = reinterpret_cast<float4*>(&g_a[(size_t)n * NH]);
    float4* ep = reinterpret_cast<float4*>(&g_e[(size_t)n * NH]);

#pragma unroll 2
    for (int og = 0; og < 16; og++) {
        float4 acc = b1v[og];
#pragma unroll 8
        for (int f = 0; f < 64; f++) {
            float x = hv[f];
            float4 wv = wA[f*16 + og];
            acc.x += x*wv.x; acc.y += x*wv.y; acc.z += x*wv.z; acc.w += x*wv.w;
        }
        ap[og] = acc;
    }
#pragma unroll 2
    for (int og = 0; og < 16; og++) {
        float4 acc = make_float4(0.f, 0.f, 0.f, 0.f);
#pragma unroll 8
        for (int f = 0; f < 64; f++) {
            float x = hv[f];
            float4 wv = wB[f*16 + og];
            acc.x += x*wv.x; acc.y += x*wv.y; acc.z += x*wv.z; acc.w += x*wv.w;
        }
        ep[og] = acc;
    }
}

// ---------------- msg: hidden = relu(a_i + e_j - e_i); out = max_k hidden@W2+b2
// block = 128 threads = 4 warps; warp handles one node. GEMM uses fma.rn.f32x2
// packed along k (pairs come directly from the 16B hid loads).
__global__ void __launch_bounds__(128) msg_kernel(
    const float* __restrict__ w2, const float* __restrict__ b2,
    float* __restrict__ hout)
{
    __shared__ float w2s[64*64];
    __shared__ float hidden[4][64*HPAD];     // [warp][o*HPAD + k]
    for (int q = threadIdx.x; q < 64*64; q += 128) w2s[q] = w2[q];
    __syncthreads();

    int warp = threadIdx.x >> 5;
    int l    = threadIdx.x & 31;
    int i    = blockIdx.x * 4 + warp;

    float a0 = g_a[(size_t)i*NH + l],      a1 = g_a[(size_t)i*NH + 32 + l];
    float e0 = g_e[(size_t)i*NH + l],      e1 = g_e[(size_t)i*NH + 32 + l];
    int jreg = (l < NK) ? g_idx[(size_t)i*NK + l] : 0;

    float* hid = hidden[warp];
#pragma unroll
    for (int k = 0; k < NK; k++) {
        int j = __shfl_sync(0xffffffffu, jreg, k);
        float ej0 = g_e[(size_t)j*NH + l];
        float ej1 = g_e[(size_t)j*NH + 32 + l];
        hid[l*HPAD + k]        = fmaxf(a0 + ej0 - e0, 0.f);
        hid[(l+32)*HPAD + k]   = fmaxf(a1 + ej1 - e1, 0.f);
    }
    __syncwarp();

    unsigned long long acc2L[8], acc2H[8];
#pragma unroll
    for (int q = 0; q < 8; q++) { acc2L[q] = 0ull; acc2H[q] = 0ull; }

#pragma unroll 2
    for (int o = 0; o < 64; o++) {
        float wl = w2s[o*64 + l];
        float wh = w2s[o*64 + 32 + l];
        unsigned long long wl2 = pack2(wl, wl);
        unsigned long long wh2 = pack2(wh, wh);
        const ulonglong2* hp = reinterpret_cast<const ulonglong2*>(hid + o*HPAD);
        ulonglong2 q0 = hp[0], q1 = hp[1];
        fma2(acc2L[0], q0.x, wl2); fma2(acc2H[0], q0.x, wh2);
        fma2(acc2L[1], q0.y, wl2); fma2(acc2H[1], q0.y, wh2);
        fma2(acc2L[2], q1.x, wl2); fma2(acc2H[2], q1.x, wh2);
        fma2(acc2L[3], q1.y, wl2); fma2(acc2H[3], q1.y, wh2);
        ulonglong2 q2 = hp[2], q3 = hp[3];
        fma2(acc2L[4], q2.x, wl2); fma2(acc2H[4], q2.x, wh2);
        fma2(acc2L[5], q2.y, wl2); fma2(acc2H[5], q2.y, wh2);
        fma2(acc2L[6], q3.x, wl2); fma2(acc2H[6], q3.x, wh2);
        fma2(acc2L[7], q3.y, wl2); fma2(acc2H[7], q3.y, wh2);
    }

    float2 pL = unpack2(acc2L[0]);
    float2 pH = unpack2(acc2H[0]);
    float m0 = fmaxf(pL.x, pL.y);
    float m1 = fmaxf(pH.x, pH.y);
#pragma unroll
    for (int q = 1; q < 8; q++) {
        pL = unpack2(acc2L[q]); pH = unpack2(acc2H[q]);
        m0 = fmaxf(m0, fmaxf(pL.x, pL.y));
        m1 = fmaxf(m1, fmaxf(pH.x, pH.y));
    }
    m0 += b2[l];
    m1 += b2[32 + l];

    hout[(size_t)i*NH + l]      = m0;
    hout[(size_t)i*NH + 32 + l] = m1;

    float s = m0*m0 + m1*m1;
#pragma unroll
    for (int off = 16; off; off >>= 1) s += __shfl_xor_sync(0xffffffffu, s, off);
    if (l == 0) g_sq[i] = s;
}

// ---------------- pool + output MLP -----------------------------------------
__global__ void __launch_bounds__(256) pool_kernel(
    const float* __restrict__ h,
    const float* __restrict__ w1, const float* __restrict__ b1,
    const float* __restrict__ w2, const float* __restrict__ b2,
    float* __restrict__ out)
{
    __shared__ float part[256];
    __shared__ float g[64];
    int b = blockIdx.x, tid = threadIdx.x;
    int c = tid & 63, rb = tid >> 6;
    float s = 0.f;
    for (int r = rb; r < NM; r += 4) s += h[(size_t)(b*NM + r)*NH + c];
    part[tid] = s;
    __syncthreads();
    if (tid < 64) g[tid] = (part[tid] + part[tid+64] + part[tid+128] + part[tid+192]) * (1.f/NM);
    __syncthreads();
    if (tid < 32) {
        float acc = b1[tid];
#pragma unroll 8
        for (int f = 0; f < 64; f++) acc += g[f] * w1[f*32 + tid];
        acc = fmaxf(acc, 0.f);
        acc *= w2[tid];
#pragma unroll
        for (int off = 16; off; off >>= 1) acc += __shfl_xor_sync(0xffffffffu, acc, off);
        if (tid == 0) out[b] = acc + b2[0];
    }
}

// ---------------- launch -----------------------------------------------------
extern "C" void kernel_launch(void* const* d_in, const int* in_sizes, int n_in,
                              void* d_out, int out_size)
{
    const float* x      = (const float*)d_in[0];
    const float* enc_w1 = (const float*)d_in[2];
    const float* enc_b1 = (const float*)d_in[3];
    const float* enc_w2 = (const float*)d_in[4];
    const float* enc_b2 = (const float*)d_in[5];
    const float* ec1_w1 = (const float*)d_in[6];
    const float* ec1_b1 = (const float*)d_in[7];
    const float* ec1_w2 = (const float*)d_in[8];
    const float* ec1_b2 = (const float*)d_in[9];
    const float* ec2_w1 = (const float*)d_in[10];
    const float* ec2_b1 = (const float*)d_in[11];
    const float* ec2_w2 = (const float*)d_in[12];
    const float* ec2_b2 = (const float*)d_in[13];
    const float* out_w1 = (const float*)d_in[14];
    const float* out_b1 = (const float*)d_in[15];
    const float* out_w2 = (const float*)d_in[16];
    const float* out_b2 = (const float*)d_in[17];
    float* out = (float*)d_out;

    float *h0, *h1;
    cudaGetSymbolAddress((void**)&h0, g_h0);
    cudaGetSymbolAddress((void**)&h1, g_h1);

    // encoder -> h0 (+ sqnorms)
    enc_kernel<<<NN/256, 256>>>(x, enc_w1, enc_b1, enc_w2, enc_b2);
    // EdgeConv 1
    knn_kernel<<<NB*8, 128>>>(h0);
    prep_kernel<<<NN/256, 256>>>(h0, ec1_w1, ec1_b1);
    msg_kernel<<<NN/4, 128>>>(ec1_w2, ec1_b2, h1);
    // EdgeConv 2
    knn_kernel<<<NB*8, 128>>>(h1);
    prep_kernel<<<NN/256, 256>>>(h1, ec2_w1, ec2_b1);
    msg_kernel<<<NN/4, 128>>>(ec2_w2, ec2_b2, h0);   // reuse h0 as h2
    // pool + output MLP
    pool_kernel<<<NB, 256>>>(h0, out_w1, out_b1, out_w2, out_b2, out);
}

// round 11
// speedup vs baseline: 1.2454x; 1.1723x over previous
#include <cuda_runtime.h>
#include <mma.h>
#include <math_constants.h>

using namespace nvcuda;

#define NB 64
#define NM 1024
#define NN (NB*NM)      // 65536 nodes
#define NH 64
#define NK 16
#define HPAD 20         // padded k-stride for transposed hidden tile (msg)
#define CH 32           // knn candidate chunk
#define DLD 36          // dist tile leading dim (mult of 4 for wmma store)

// ---------------- device scratch (static globals; no allocation) -------------
__device__ float g_h0[NN*NH];
__device__ float g_h1[NN*NH];
__device__ float g_a [NN*NH];
__device__ float g_e [NN*NH];
__device__ float g_sq[NN];
__device__ int   g_idx[NN*NK];

// ---------------- encoder: x[4] -> 32 -> 64 (ReLU both), + sqnorm ------------
__global__ void __launch_bounds__(256) enc_kernel(
    const float* __restrict__ x,
    const float* __restrict__ w1, const float* __restrict__ b1,
    const float* __restrict__ w2, const float* __restrict__ b2)
{
    __shared__ float w1s[4*32];
    __shared__ float b1s[32];
    __shared__ float w2s[32*64];
    __shared__ float b2s[64];
    int tid = threadIdx.x;
    if (tid < 128) w1s[tid] = w1[tid];
    if (tid < 32)  b1s[tid] = b1[tid];
    for (int q = tid; q < 32*64; q += 256) w2s[q] = w2[q];
    if (tid < 64)  b2s[tid] = b2[tid];
    __syncthreads();

    int n = blockIdx.x * 256 + tid;
    float4 xv = reinterpret_cast<const float4*>(x)[n];

    float hid[32];
#pragma unroll
    for (int o = 0; o < 32; o++) {
        float acc = b1s[o];
        acc += xv.x * w1s[o];
        acc += xv.y * w1s[32 + o];
        acc += xv.z * w1s[64 + o];
        acc += xv.w * w1s[96 + o];
        hid[o] = fmaxf(acc, 0.f);
    }

    float sq = 0.f;
    float4* outp = reinterpret_cast<float4*>(&g_h0[(size_t)n * NH]);
    const float4* w2v = reinterpret_cast<const float4*>(w2s);
    const float4* b2v = reinterpret_cast<const float4*>(b2s);
#pragma unroll
    for (int og = 0; og < 16; og++) {
        float4 acc = b2v[og];
#pragma unroll
        for (int j = 0; j < 32; j++) {
            float hv = hid[j];
            float4 wv = w2v[j*16 + og];
            acc.x += hv * wv.x; acc.y += hv * wv.y;
            acc.z += hv * wv.z; acc.w += hv * wv.w;
        }
        acc.x = fmaxf(acc.x, 0.f); acc.y = fmaxf(acc.y, 0.f);
        acc.z = fmaxf(acc.z, 0.f); acc.w = fmaxf(acc.w, 0.f);
        sq += acc.x*acc.x + acc.y*acc.y + acc.z*acc.z + acc.w*acc.w;
        outp[og] = acc;
    }
    g_sq[n] = sq;
}

// ---------------- kNN v3: tf32 tensor-core Gram (hi/lo split) + fused top-16 -
// block = 128 threads / 4 warps, owns a 128-row strip of one batch.
// Per 32-candidate chunk: D = A @ B^T via wmma m16n16k8 tf32 with 3-pass
// hi/lo split (fp32-grade accuracy), dist tile -> smem, per-thread top-16 scan.
__global__ void __launch_bounds__(128) knn3_kernel(const float* __restrict__ h)
{
    extern __shared__ float sm[];
    float* A_hi = sm;                    // [128][64]
    float* A_lo = A_hi + 128*64;         // [128][64]
    float* B_hi = A_lo + 128*64;         // [CH][64]
    float* B_lo = B_hi + CH*64;          // [CH][64]
    float* Ds   = B_lo + CH*64;          // [128][DLD]
    float* sqs  = Ds + 128*DLD;          // [CH]

    int tid  = threadIdx.x;
    int warp = tid >> 5;
    int b      = blockIdx.x >> 3;
    int istrip = (blockIdx.x & 7) * 128;
    int il     = istrip + tid;           // local row this thread owns
    const float* hb = h + (size_t)b * NM * NH;

    // fill A_hi/A_lo: thread converts its own row
    {
        const float4* src = reinterpret_cast<const float4*>(hb + (size_t)il * NH);
#pragma unroll
        for (int f = 0; f < 16; f++) {
            float4 v = src[f];
            float hi;
            hi = wmma::__float_to_tf32(v.x); A_hi[tid*64+4*f+0] = hi; A_lo[tid*64+4*f+0] = wmma::__float_to_tf32(v.x - hi);
            hi = wmma::__float_to_tf32(v.y); A_hi[tid*64+4*f+1] = hi; A_lo[tid*64+4*f+1] = wmma::__float_to_tf32(v.y - hi);
            hi = wmma::__float_to_tf32(v.z); A_hi[tid*64+4*f+2] = hi; A_lo[tid*64+4*f+2] = wmma::__float_to_tf32(v.z - hi);
            hi = wmma::__float_to_tf32(v.w); A_hi[tid*64+4*f+3] = hi; A_lo[tid*64+4*f+3] = wmma::__float_to_tf32(v.w - hi);
        }
    }

    float dist[NK]; int idx[NK];
#pragma unroll
    for (int k = 0; k < NK; k++) { dist[k] = CUDART_INF_F; idx[k] = 0; }
    float worst = CUDART_INF_F; int wpos = 0;

    wmma::fragment<wmma::accumulator, 16, 16, 8, float> acc[2][2];

    for (int jb = 0; jb < NM; jb += CH) {
        __syncthreads();   // prev-chunk scan (Ds/sqs reads) done before refill

        // fill B_hi/B_lo chunk + sqs: 4 threads per candidate row
        {
            int r  = tid >> 2;              // candidate 0..31
            int fq = (tid & 3) * 4;         // float4 slot 0,4,8,12
            const float4* src = reinterpret_cast<const float4*>(hb + (size_t)(jb + r) * NH);
#pragma unroll
            for (int u = 0; u < 4; u++) {
                float4 v = src[fq + u];
                int base = r*64 + (fq + u)*4;
                float hi;
                hi = wmma::__float_to_tf32(v.x); B_hi[base+0] = hi; B_lo[base+0] = wmma::__float_to_tf32(v.x - hi);
                hi = wmma::__float_to_tf32(v.y); B_hi[base+1] = hi; B_lo[base+1] = wmma::__float_to_tf32(v.y - hi);
                hi = wmma::__float_to_tf32(v.z); B_hi[base+2] = hi; B_lo[base+2] = wmma::__float_to_tf32(v.z - hi);
                hi = wmma::__float_to_tf32(v.w); B_hi[base+3] = hi; B_lo[base+3] = wmma::__float_to_tf32(v.w - hi);
            }
            if (tid < CH) sqs[tid] = g_sq[b*NM + jb + tid];
        }
        __syncthreads();

#pragma unroll
        for (int mt = 0; mt < 2; mt++)
#pragma unroll
            for (int nt = 0; nt < 2; nt++) wmma::fill_fragment(acc[mt][nt], 0.f);

#pragma unroll
        for (int ks = 0; ks < 8; ks++) {
            wmma::fragment<wmma::matrix_a, 16, 16, 8, wmma::precision::tf32, wmma::row_major> ahi[2], alo[2];
            wmma::fragment<wmma::matrix_b, 16, 16, 8, wmma::precision::tf32, wmma::col_major> bhi[2], blo[2];
#pragma unroll
            for (int mt = 0; mt < 2; mt++) {
                int row0 = warp*32 + mt*16;
                wmma::load_matrix_sync(ahi[mt], A_hi + row0*64 + ks*8, 64);
                wmma::load_matrix_sync(alo[mt], A_lo + row0*64 + ks*8, 64);
            }
#pragma unroll
            for (int nt = 0; nt < 2; nt++) {
                wmma::load_matrix_sync(bhi[nt], B_hi + nt*16*64 + ks*8, 64);
                wmma::load_matrix_sync(blo[nt], B_lo + nt*16*64 + ks*8, 64);
            }
#pragma unroll
            for (int mt = 0; mt < 2; mt++)
#pragma unroll
                for (int nt = 0; nt < 2; nt++) {
                    wmma::mma_sync(acc[mt][nt], ahi[mt], bhi[nt], acc[mt][nt]);
                    wmma::mma_sync(acc[mt][nt], ahi[mt], blo[nt], acc[mt][nt]);
                    wmma::mma_sync(acc[mt][nt], alo[mt], bhi[nt], acc[mt][nt]);
                }
        }

#pragma unroll
        for (int mt = 0; mt < 2; mt++)
#pragma unroll
            for (int nt = 0; nt < 2; nt++)
                wmma::store_matrix_sync(Ds + (warp*32 + mt*16)*DLD + nt*16,
                                        acc[mt][nt], DLD, wmma::mem_row_major);
        __syncthreads();

        // selection: thread tid scans row tid of the dist tile
#pragma unroll 4
        for (int jj = 0; jj < CH; jj++) {
            float d = sqs[jj] - 2.f * Ds[tid*DLD + jj];
            int j = jb + jj;
            if (d < worst && j != il) {
#pragma unroll
                for (int k = 0; k < NK; k++) if (k == wpos) { dist[k] = d; idx[k] = j; }
                worst = dist[0]; wpos = 0;
#pragma unroll
                for (int k = 1; k < NK; k++) if (dist[k] > worst) { worst = dist[k]; wpos = k; }
            }
        }
    }

    int i = b*NM + il;
#pragma unroll
    for (int k = 0; k < NK; k++) g_idx[(size_t)i*NK + k] = b*NM + idx[k];
}

// ---------------- prep: a = h@W1[:64] + b1,  e = h@W1[64:] -------------------
__global__ void __launch_bounds__(256) prep_kernel(
    const float* __restrict__ h,
    const float* __restrict__ w1, const float* __restrict__ b1)
{
    __shared__ float w1s[128*64];
    __shared__ float b1s[64];
    for (int q = threadIdx.x; q < 128*64; q += 256) w1s[q] = w1[q];
    if (threadIdx.x < 64) b1s[threadIdx.x] = b1[threadIdx.x];
    __syncthreads();

    int n = blockIdx.x * 256 + threadIdx.x;
    float hv[NH];
    {
        const float4* src = reinterpret_cast<const float4*>(h + (size_t)n * NH);
#pragma unroll
        for (int f = 0; f < 16; f++) {
            float4 v = src[f];
            hv[f*4+0] = v.x; hv[f*4+1] = v.y; hv[f*4+2] = v.z; hv[f*4+3] = v.w;
        }
    }

    const float4* wA = reinterpret_cast<const float4*>(w1s);            // rows 0..63
    const float4* wB = reinterpret_cast<const float4*>(w1s + 64*64);    // rows 64..127
    const float4* b1v = reinterpret_cast<const float4*>(b1s);
    float4* ap = reinterpret_cast<float4*>(&g_a[(size_t)n * NH]);
    float4* ep = reinterpret_cast<float4*>(&g_e[(size_t)n * NH]);

#pragma unroll 2
    for (int og = 0; og < 16; og++) {
        float4 acc = b1v[og];
#pragma unroll 8
        for (int f = 0; f < 64; f++) {
            float x = hv[f];
            float4 wv = wA[f*16 + og];
            acc.x += x*wv.x; acc.y += x*wv.y; acc.z += x*wv.z; acc.w += x*wv.w;
        }
        ap[og] = acc;
    }
#pragma unroll 2
    for (int og = 0; og < 16; og++) {
        float4 acc = make_float4(0.f, 0.f, 0.f, 0.f);
#pragma unroll 8
        for (int f = 0; f < 64; f++) {
            float x = hv[f];
            float4 wv = wB[f*16 + og];
            acc.x += x*wv.x; acc.y += x*wv.y; acc.z += x*wv.z; acc.w += x*wv.w;
        }
        ep[og] = acc;
    }
}

// ---------------- msg: hidden = relu(a_i + e_j - e_i); out = max_k hidden@W2+b2
// block = 128 threads = 4 warps; warp handles one node. (R4 scalar version.)
__global__ void __launch_bounds__(128) msg_kernel(
    const float* __restrict__ w2, const float* __restrict__ b2,
    float* __restrict__ hout)
{
    __shared__ float w2s[64*64];
    __shared__ float hidden[4][64*HPAD];     // [warp][o*HPAD + k]
    for (int q = threadIdx.x; q < 64*64; q += 128) w2s[q] = w2[q];
    __syncthreads();

    int warp = threadIdx.x >> 5;
    int l    = threadIdx.x & 31;
    int i    = blockIdx.x * 4 + warp;

    float a0 = g_a[(size_t)i*NH + l],      a1 = g_a[(size_t)i*NH + 32 + l];
    float e0 = g_e[(size_t)i*NH + l],      e1 = g_e[(size_t)i*NH + 32 + l];
    int jreg = (l < NK) ? g_idx[(size_t)i*NK + l] : 0;

    float* hid = hidden[warp];
#pragma unroll
    for (int k = 0; k < NK; k++) {
        int j = __shfl_sync(0xffffffffu, jreg, k);
        float ej0 = g_e[(size_t)j*NH + l];
        float ej1 = g_e[(size_t)j*NH + 32 + l];
        hid[l*HPAD + k]        = fmaxf(a0 + ej0 - e0, 0.f);
        hid[(l+32)*HPAD + k]   = fmaxf(a1 + ej1 - e1, 0.f);
    }
    __syncwarp();

    float accL[NK], accH[NK];
#pragma unroll
    for (int k = 0; k < NK; k++) { accL[k] = 0.f; accH[k] = 0.f; }

#pragma unroll 2
    for (int o = 0; o < 64; o++) {
        float wl = w2s[o*64 + l];
        float wh = w2s[o*64 + 32 + l];
        const float4* hp = reinterpret_cast<const float4*>(hid + o*HPAD);
        float4 h0v = hp[0], h1v = hp[1], h2v = hp[2], h3v = hp[3];
        float hk[16] = { h0v.x,h0v.y,h0v.z,h0v.w, h1v.x,h1v.y,h1v.z,h1v.w,
                         h2v.x,h2v.y,h2v.z,h2v.w, h3v.x,h3v.y,h3v.z,h3v.w };
#pragma unroll
        for (int k = 0; k < NK; k++) {
            accL[k] += hk[k] * wl;
            accH[k] += hk[k] * wh;
        }
    }

    float m0 = accL[0], m1 = accH[0];
#pragma unroll
    for (int k = 1; k < NK; k++) { m0 = fmaxf(m0, accL[k]); m1 = fmaxf(m1, accH[k]); }
    m0 += b2[l];
    m1 += b2[32 + l];

    hout[(size_t)i*NH + l]      = m0;
    hout[(size_t)i*NH + 32 + l] = m1;

    float s = m0*m0 + m1*m1;
#pragma unroll
    for (int off = 16; off; off >>= 1) s += __shfl_xor_sync(0xffffffffu, s, off);
    if (l == 0) g_sq[i] = s;
}

// ---------------- pool + output MLP -----------------------------------------
__global__ void __launch_bounds__(256) pool_kernel(
    const float* __restrict__ h,
    const float* __restrict__ w1, const float* __restrict__ b1,
    const float* __restrict__ w2, const float* __restrict__ b2,
    float* __restrict__ out)
{
    __shared__ float part[256];
    __shared__ float g[64];
    int b = blockIdx.x, tid = threadIdx.x;
    int c = tid & 63, rb = tid >> 6;
    float s = 0.f;
    for (int r = rb; r < NM; r += 4) s += h[(size_t)(b*NM + r)*NH + c];
    part[tid] = s;
    __syncthreads();
    if (tid < 64) g[tid] = (part[tid] + part[tid+64] + part[tid+128] + part[tid+192]) * (1.f/NM);
    __syncthreads();
    if (tid < 32) {
        float acc = b1[tid];
#pragma unroll 8
        for (int f = 0; f < 64; f++) acc += g[f] * w1[f*32 + tid];
        acc = fmaxf(acc, 0.f);
        acc *= w2[tid];
#pragma unroll
        for (int off = 16; off; off >>= 1) acc += __shfl_xor_sync(0xffffffffu, acc, off);
        if (tid == 0) out[b] = acc + b2[0];
    }
}

// ---------------- launch -----------------------------------------------------
extern "C" void kernel_launch(void* const* d_in, const int* in_sizes, int n_in,
                              void* d_out, int out_size)
{
    const float* x      = (const float*)d_in[0];
    const float* enc_w1 = (const float*)d_in[2];
    const float* enc_b1 = (const float*)d_in[3];
    const float* enc_w2 = (const float*)d_in[4];
    const float* enc_b2 = (const float*)d_in[5];
    const float* ec1_w1 = (const float*)d_in[6];
    const float* ec1_b1 = (const float*)d_in[7];
    const float* ec1_w2 = (const float*)d_in[8];
    const float* ec1_b2 = (const float*)d_in[9];
    const float* ec2_w1 = (const float*)d_in[10];
    const float* ec2_b1 = (const float*)d_in[11];
    const float* ec2_w2 = (const float*)d_in[12];
    const float* ec2_b2 = (const float*)d_in[13];
    const float* out_w1 = (const float*)d_in[14];
    const float* out_b1 = (const float*)d_in[15];
    const float* out_w2 = (const float*)d_in[16];
    const float* out_b2 = (const float*)d_in[17];
    float* out = (float*)d_out;

    float *h0, *h1;
    cudaGetSymbolAddress((void**)&h0, g_h0);
    cudaGetSymbolAddress((void**)&h1, g_h1);

    const int KNN_SMEM = (128*64*2 + CH*64*2 + 128*DLD + CH) * sizeof(float);  // 100480 B
    cudaFuncSetAttribute(knn3_kernel, cudaFuncAttributeMaxDynamicSharedMemorySize, KNN_SMEM);

    // encoder -> h0 (+ sqnorms)
    enc_kernel<<<NN/256, 256>>>(x, enc_w1, enc_b1, enc_w2, enc_b2);
    // EdgeConv 1
    knn3_kernel<<<NB*8, 128, KNN_SMEM>>>(h0);
    prep_kernel<<<NN/256, 256>>>(h0, ec1_w1, ec1_b1);
    msg_kernel<<<NN/4, 128>>>(ec1_w2, ec1_b2, h1);
    // EdgeConv 2
    knn3_kernel<<<NB*8, 128, KNN_SMEM>>>(h1);
    prep_kernel<<<NN/256, 256>>>(h1, ec2_w1, ec2_b1);
    msg_kernel<<<NN/4, 128>>>(ec2_w2, ec2_b2, h0);   // reuse h0 as h2
    // pool + output MLP
    pool_kernel<<<NB, 256>>>(h0, out_w1, out_b1, out_w2, out_b2, out);
}

// round 12
// speedup vs baseline: 1.6397x; 1.3167x over previous
#include <cuda_runtime.h>
#include <cuda_bf16.h>
#include <mma.h>
#include <math_constants.h>

using namespace nvcuda;

#define NB 64
#define NM 1024
#define NN (NB*NM)      // 65536 nodes
#define NH 64
#define NK 16
#define HPAD 20         // padded k-stride for transposed hidden tile (msg)
#define CH 32           // knn candidate chunk
#define DLD 36          // dist tile leading dim (144 B, 16B-multiple for wmma store)

// ---------------- device scratch (static globals; no allocation) -------------
__device__ float g_h0[NN*NH];
__device__ float g_h1[NN*NH];
__device__ float g_a [NN*NH];
__device__ float g_e [NN*NH];
__device__ float g_sq[NN];
__device__ int   g_idx[NN*NK];

// ---------------- encoder: x[4] -> 32 -> 64 (ReLU both), + sqnorm ------------
__global__ void __launch_bounds__(256) enc_kernel(
    const float* __restrict__ x,
    const float* __restrict__ w1, const float* __restrict__ b1,
    const float* __restrict__ w2, const float* __restrict__ b2)
{
    __shared__ float w1s[4*32];
    __shared__ float b1s[32];
    __shared__ float w2s[32*64];
    __shared__ float b2s[64];
    int tid = threadIdx.x;
    if (tid < 128) w1s[tid] = w1[tid];
    if (tid < 32)  b1s[tid] = b1[tid];
    for (int q = tid; q < 32*64; q += 256) w2s[q] = w2[q];
    if (tid < 64)  b2s[tid] = b2[tid];
    __syncthreads();

    int n = blockIdx.x * 256 + tid;
    float4 xv = reinterpret_cast<const float4*>(x)[n];

    float hid[32];
#pragma unroll
    for (int o = 0; o < 32; o++) {
        float acc = b1s[o];
        acc += xv.x * w1s[o];
        acc += xv.y * w1s[32 + o];
        acc += xv.z * w1s[64 + o];
        acc += xv.w * w1s[96 + o];
        hid[o] = fmaxf(acc, 0.f);
    }

    float sq = 0.f;
    float4* outp = reinterpret_cast<float4*>(&g_h0[(size_t)n * NH]);
    const float4* w2v = reinterpret_cast<const float4*>(w2s);
    const float4* b2v = reinterpret_cast<const float4*>(b2s);
#pragma unroll
    for (int og = 0; og < 16; og++) {
        float4 acc = b2v[og];
#pragma unroll
        for (int j = 0; j < 32; j++) {
            float hv = hid[j];
            float4 wv = w2v[j*16 + og];
            acc.x += hv * wv.x; acc.y += hv * wv.y;
            acc.z += hv * wv.z; acc.w += hv * wv.w;
        }
        acc.x = fmaxf(acc.x, 0.f); acc.y = fmaxf(acc.y, 0.f);
        acc.z = fmaxf(acc.z, 0.f); acc.w = fmaxf(acc.w, 0.f);
        sq += acc.x*acc.x + acc.y*acc.y + acc.z*acc.z + acc.w*acc.w;
        outp[og] = acc;
    }
    g_sq[n] = sq;
}

// ---------------- kNN v4: bf16 tensor-core Gram (hi/lo split) + fused top-16 -
// block = 128 threads / 4 warps, owns a 128-row strip of one batch.
// D = A@B^T via wmma m16n16k16 bf16, 3-pass hi/lo split:
//   dot = hi_a.hi_b + hi_a.lo_b + lo_a.hi_b  (lo.lo dropped, ~2^-18 relative)
// bf16 products are exact in fp32 accumulation, so error < tf32-split (passed R11).
// bf16 fragment loads use LDSM (fast), unlike tf32's scalar-LDS lowering.
__global__ void __launch_bounds__(128) knn4_kernel(const float* __restrict__ h)
{
    extern __shared__ char smraw[];
    float* Ds  = reinterpret_cast<float*>(smraw);            // [128][DLD] 18432 B
    float* sqs = Ds + 128*DLD;                               // [CH]       128 B
    __nv_bfloat16* A_hi = reinterpret_cast<__nv_bfloat16*>(sqs + CH);  // [128][64]
    __nv_bfloat16* A_lo = A_hi + 128*64;                     // [128][64]
    __nv_bfloat16* B_hi = A_lo + 128*64;                     // [CH][64]
    __nv_bfloat16* B_lo = B_hi + CH*64;                      // [CH][64]

    int tid  = threadIdx.x;
    int warp = tid >> 5;
    int b      = blockIdx.x >> 3;
    int istrip = (blockIdx.x & 7) * 128;
    int il     = istrip + tid;           // local row this thread owns
    const float* hb = h + (size_t)b * NM * NH;

    // fill A_hi/A_lo: thread converts its own row
    {
        const float4* src = reinterpret_cast<const float4*>(hb + (size_t)il * NH);
#pragma unroll
        for (int f = 0; f < 16; f++) {
            float4 v = src[f];
            __nv_bfloat16 bh;
            bh = __float2bfloat16(v.x); A_hi[tid*64+4*f+0] = bh; A_lo[tid*64+4*f+0] = __float2bfloat16(v.x - __bfloat162float(bh));
            bh = __float2bfloat16(v.y); A_hi[tid*64+4*f+1] = bh; A_lo[tid*64+4*f+1] = __float2bfloat16(v.y - __bfloat162float(bh));
            bh = __float2bfloat16(v.z); A_hi[tid*64+4*f+2] = bh; A_lo[tid*64+4*f+2] = __float2bfloat16(v.z - __bfloat162float(bh));
            bh = __float2bfloat16(v.w); A_hi[tid*64+4*f+3] = bh; A_lo[tid*64+4*f+3] = __float2bfloat16(v.w - __bfloat162float(bh));
        }
    }

    float dist[NK]; int idx[NK];
#pragma unroll
    for (int k = 0; k < NK; k++) { dist[k] = CUDART_INF_F; idx[k] = 0; }
    float worst = CUDART_INF_F; int wpos = 0;

    wmma::fragment<wmma::accumulator, 16, 16, 16, float> acc[2][2];

    for (int jb = 0; jb < NM; jb += CH) {
        __syncthreads();   // prev-chunk scan (Ds/sqs reads) done before refill

        // fill B_hi/B_lo chunk + sqs: 4 threads per candidate row
        {
            int r  = tid >> 2;              // candidate 0..31
            int fq = (tid & 3) * 4;         // float4 slot 0,4,8,12
            const float4* src = reinterpret_cast<const float4*>(hb + (size_t)(jb + r) * NH);
#pragma unroll
            for (int u = 0; u < 4; u++) {
                float4 v = src[fq + u];
                int base = r*64 + (fq + u)*4;
                __nv_bfloat16 bh;
                bh = __float2bfloat16(v.x); B_hi[base+0] = bh; B_lo[base+0] = __float2bfloat16(v.x - __bfloat162float(bh));
                bh = __float2bfloat16(v.y); B_hi[base+1] = bh; B_lo[base+1] = __float2bfloat16(v.y - __bfloat162float(bh));
                bh = __float2bfloat16(v.z); B_hi[base+2] = bh; B_lo[base+2] = __float2bfloat16(v.z - __bfloat162float(bh));
                bh = __float2bfloat16(v.w); B_hi[base+3] = bh; B_lo[base+3] = __float2bfloat16(v.w - __bfloat162float(bh));
            }
            if (tid < CH) sqs[tid] = g_sq[b*NM + jb + tid];
        }
        __syncthreads();

#pragma unroll
        for (int mt = 0; mt < 2; mt++)
#pragma unroll
            for (int nt = 0; nt < 2; nt++) wmma::fill_fragment(acc[mt][nt], 0.f);

#pragma unroll
        for (int ks = 0; ks < 4; ks++) {            // K=64 in 4 steps of 16
            wmma::fragment<wmma::matrix_a, 16, 16, 16, __nv_bfloat16, wmma::row_major> ahi[2], alo[2];
            wmma::fragment<wmma::matrix_b, 16, 16, 16, __nv_bfloat16, wmma::col_major> bhi[2], blo[2];
#pragma unroll
            for (int mt = 0; mt < 2; mt++) {
                int row0 = warp*32 + mt*16;
                wmma::load_matrix_sync(ahi[mt], A_hi + row0*64 + ks*16, 64);
                wmma::load_matrix_sync(alo[mt], A_lo + row0*64 + ks*16, 64);
            }
#pragma unroll
            for (int nt = 0; nt < 2; nt++) {
                wmma::load_matrix_sync(bhi[nt], B_hi + nt*16*64 + ks*16, 64);
                wmma::load_matrix_sync(blo[nt], B_lo + nt*16*64 + ks*16, 64);
            }
#pragma unroll
            for (int mt = 0; mt < 2; mt++)
#pragma unroll
                for (int nt = 0; nt < 2; nt++) {
                    wmma::mma_sync(acc[mt][nt], ahi[mt], bhi[nt], acc[mt][nt]);
                    wmma::mma_sync(acc[mt][nt], ahi[mt], blo[nt], acc[mt][nt]);
                    wmma::mma_sync(acc[mt][nt], alo[mt], bhi[nt], acc[mt][nt]);
                }
        }

#pragma unroll
        for (int mt = 0; mt < 2; mt++)
#pragma unroll
            for (int nt = 0; nt < 2; nt++)
                wmma::store_matrix_sync(Ds + (warp*32 + mt*16)*DLD + nt*16,
                                        acc[mt][nt], DLD, wmma::mem_row_major);
        __syncthreads();

        // selection: thread tid scans row tid of the dist tile
#pragma unroll 4
        for (int jj = 0; jj < CH; jj++) {
            float d = sqs[jj] - 2.f * Ds[tid*DLD + jj];
            int j = jb + jj;
            if (d < worst && j != il) {
#pragma unroll
                for (int k = 0; k < NK; k++) if (k == wpos) { dist[k] = d; idx[k] = j; }
                worst = dist[0]; wpos = 0;
#pragma unroll
                for (int k = 1; k < NK; k++) if (dist[k] > worst) { worst = dist[k]; wpos = k; }
            }
        }
    }

    int i = b*NM + il;
#pragma unroll
    for (int k = 0; k < NK; k++) g_idx[(size_t)i*NK + k] = b*NM + idx[k];
}

// ---------------- prep: a = h@W1[:64] + b1,  e = h@W1[64:] -------------------
__global__ void __launch_bounds__(256) prep_kernel(
    const float* __restrict__ h,
    const float* __restrict__ w1, const float* __restrict__ b1)
{
    __shared__ float w1s[128*64];
    __shared__ float b1s[64];
    for (int q = threadIdx.x; q < 128*64; q += 256) w1s[q] = w1[q];
    if (threadIdx.x < 64) b1s[threadIdx.x] = b1[threadIdx.x];
    __syncthreads();

    int n = blockIdx.x * 256 + threadIdx.x;
    float hv[NH];
    {
        const float4* src = reinterpret_cast<const float4*>(h + (size_t)n * NH);
#pragma unroll
        for (int f = 0; f < 16; f++) {
            float4 v = src[f];
            hv[f*4+0] = v.x; hv[f*4+1] = v.y; hv[f*4+2] = v.z; hv[f*4+3] = v.w;
        }
    }

    const float4* wA = reinterpret_cast<const float4*>(w1s);            // rows 0..63
    const float4* wB = reinterpret_cast<const float4*>(w1s + 64*64);    // rows 64..127
    const float4* b1v = reinterpret_cast<const float4*>(b1s);
    float4* ap = reinterpret_cast<float4*>(&g_a[(size_t)n * NH]);
    float4* ep = reinterpret_cast<float4*>(&g_e[(size_t)n * NH]);

#pragma unroll 2
    for (int og = 0; og < 16; og++) {
        float4 acc = b1v[og];
#pragma unroll 8
        for (int f = 0; f < 64; f++) {
            float x = hv[f];
            float4 wv = wA[f*16 + og];
            acc.x += x*wv.x; acc.y += x*wv.y; acc.z += x*wv.z; acc.w += x*wv.w;
        }
        ap[og] = acc;
    }
#pragma unroll 2
    for (int og = 0; og < 16; og++) {
        float4 acc = make_float4(0.f, 0.f, 0.f, 0.f);
#pragma unroll 8
        for (int f = 0; f < 64; f++) {
            float x = hv[f];
            float4 wv = wB[f*16 + og];
            acc.x += x*wv.x; acc.y += x*wv.y; acc.z += x*wv.z; acc.w += x*wv.w;
        }
        ep[og] = acc;
    }
}

// ---------------- msg: hidden = relu(a_i + e_j - e_i); out = max_k hidden@W2+b2
// block = 128 threads = 4 warps; warp handles one node. (R4 scalar version.)
__global__ void __launch_bounds__(128) msg_kernel(
    const float* __restrict__ w2, const float* __restrict__ b2,
    float* __restrict__ hout)
{
    __shared__ float w2s[64*64];
    __shared__ float hidden[4][64*HPAD];     // [warp][o*HPAD + k]
    for (int q = threadIdx.x; q < 64*64; q += 128) w2s[q] = w2[q];
    __syncthreads();

    int warp = threadIdx.x >> 5;
    int l    = threadIdx.x & 31;
    int i    = blockIdx.x * 4 + warp;

    float a0 = g_a[(size_t)i*NH + l],      a1 = g_a[(size_t)i*NH + 32 + l];
    float e0 = g_e[(size_t)i*NH + l],      e1 = g_e[(size_t)i*NH + 32 + l];
    int jreg = (l < NK) ? g_idx[(size_t)i*NK + l] : 0;

    float* hid = hidden[warp];
#pragma unroll
    for (int k = 0; k < NK; k++) {
        int j = __shfl_sync(0xffffffffu, jreg, k);
        float ej0 = g_e[(size_t)j*NH + l];
        float ej1 = g_e[(size_t)j*NH + 32 + l];
        hid[l*HPAD + k]        = fmaxf(a0 + ej0 - e0, 0.f);
        hid[(l+32)*HPAD + k]   = fmaxf(a1 + ej1 - e1, 0.f);
    }
    __syncwarp();

    float accL[NK], accH[NK];
#pragma unroll
    for (int k = 0; k < NK; k++) { accL[k] = 0.f; accH[k] = 0.f; }

#pragma unroll 2
    for (int o = 0; o < 64; o++) {
        float wl = w2s[o*64 + l];
        float wh = w2s[o*64 + 32 + l];
        const float4* hp = reinterpret_cast<const float4*>(hid + o*HPAD);
        float4 h0v = hp[0], h1v = hp[1], h2v = hp[2], h3v = hp[3];
        float hk[16] = { h0v.x,h0v.y,h0v.z,h0v.w, h1v.x,h1v.y,h1v.z,h1v.w,
                         h2v.x,h2v.y,h2v.z,h2v.w, h3v.x,h3v.y,h3v.z,h3v.w };
#pragma unroll
        for (int k = 0; k < NK; k++) {
            accL[k] += hk[k] * wl;
            accH[k] += hk[k] * wh;
        }
    }

    float m0 = accL[0], m1 = accH[0];
#pragma unroll
    for (int k = 1; k < NK; k++) { m0 = fmaxf(m0, accL[k]); m1 = fmaxf(m1, accH[k]); }
    m0 += b2[l];
    m1 += b2[32 + l];

    hout[(size_t)i*NH + l]      = m0;
    hout[(size_t)i*NH + 32 + l] = m1;

    float s = m0*m0 + m1*m1;
#pragma unroll
    for (int off = 16; off; off >>= 1) s += __shfl_xor_sync(0xffffffffu, s, off);
    if (l == 0) g_sq[i] = s;
}

// ---------------- pool + output MLP -----------------------------------------
__global__ void __launch_bounds__(256) pool_kernel(
    const float* __restrict__ h,
    const float* __restrict__ w1, const float* __restrict__ b1,
    const float* __restrict__ w2, const float* __restrict__ b2,
    float* __restrict__ out)
{
    __shared__ float part[256];
    __shared__ float g[64];
    int b = blockIdx.x, tid = threadIdx.x;
    int c = tid & 63, rb = tid >> 6;
    float s = 0.f;
    for (int r = rb; r < NM; r += 4) s += h[(size_t)(b*NM + r)*NH + c];
    part[tid] = s;
    __syncthreads();
    if (tid < 64) g[tid] = (part[tid] + part[tid+64] + part[tid+128] + part[tid+192]) * (1.f/NM);
    __syncthreads();
    if (tid < 32) {
        float acc = b1[tid];
#pragma unroll 8
        for (int f = 0; f < 64; f++) acc += g[f] * w1[f*32 + tid];
        acc = fmaxf(acc, 0.f);
        acc *= w2[tid];
#pragma unroll
        for (int off = 16; off; off >>= 1) acc += __shfl_xor_sync(0xffffffffu, acc, off);
        if (tid == 0) out[b] = acc + b2[0];
    }
}

// ---------------- launch -----------------------------------------------------
extern "C" void kernel_launch(void* const* d_in, const int* in_sizes, int n_in,
                              void* d_out, int out_size)
{
    const float* x      = (const float*)d_in[0];
    const float* enc_w1 = (const float*)d_in[2];
    const float* enc_b1 = (const float*)d_in[3];
    const float* enc_w2 = (const float*)d_in[4];
    const float* enc_b2 = (const float*)d_in[5];
    const float* ec1_w1 = (const float*)d_in[6];
    const float* ec1_b1 = (const float*)d_in[7];
    const float* ec1_w2 = (const float*)d_in[8];
    const float* ec1_b2 = (const float*)d_in[9];
    const float* ec2_w1 = (const float*)d_in[10];
    const float* ec2_b1 = (const float*)d_in[11];
    const float* ec2_w2 = (const float*)d_in[12];
    const float* ec2_b2 = (const float*)d_in[13];
    const float* out_w1 = (const float*)d_in[14];
    const float* out_b1 = (const float*)d_in[15];
    const float* out_w2 = (const float*)d_in[16];
    const float* out_b2 = (const float*)d_in[17];
    float* out = (float*)d_out;

    float *h0, *h1;
    cudaGetSymbolAddress((void**)&h0, g_h0);
    cudaGetSymbolAddress((void**)&h1, g_h1);

    // Ds + sqs (float) + A_hi/A_lo/B_hi/B_lo (bf16)
    const int KNN_SMEM = 128*DLD*4 + CH*4 + (128*64*2 + CH*64*2) * 2;   // 43136 B
    cudaFuncSetAttribute(knn4_kernel, cudaFuncAttributeMaxDynamicSharedMemorySize, KNN_SMEM);

    // encoder -> h0 (+ sqnorms)
    enc_kernel<<<NN/256, 256>>>(x, enc_w1, enc_b1, enc_w2, enc_b2);
    // EdgeConv 1
    knn4_kernel<<<NB*8, 128, KNN_SMEM>>>(h0);
    prep_kernel<<<NN/256, 256>>>(h0, ec1_w1, ec1_b1);
    msg_kernel<<<NN/4, 128>>>(ec1_w2, ec1_b2, h1);
    // EdgeConv 2
    knn4_kernel<<<NB*8, 128, KNN_SMEM>>>(h1);
    prep_kernel<<<NN/256, 256>>>(h1, ec2_w1, ec2_b1);
    msg_kernel<<<NN/4, 128>>>(ec2_w2, ec2_b2, h0);   // reuse h0 as h2
    // pool + output MLP
    pool_kernel<<<NB, 256>>>(h0, out_w1, out_b1, out_w2, out_b2, out);
}